// round 1
// baseline (speedup 1.0000x reference)
#include <cuda_runtime.h>
#include <math.h>

#define B_ 8
#define C_ 256
#define H_IMG 64
#define W_IMG 64
#define N_ 4096
#define HEADS_ 8
#define HD_ 32
#define SCALE_ 0.17677669529663687f   /* 32^-0.5 */

// ---------------- scratch (device globals: no allocation allowed) ----------------
__device__ float g_qkvo[(size_t)B_ * 4 * C_ * N_];   // 134 MB: [b][o(1024)][n]
__device__ float g_res [(size_t)B_ * C_ * N_];       // 33.5 MB: [b][c][n]
__device__ float g_kv  [B_ * HEADS_ * HD_ * HD_];    // [bh][d][e]
__device__ float g_kmean[B_ * C_];
__device__ float g_vmean[B_ * C_];
__device__ float g_sinT[HD_ * N_];                   // transposed trig: [d][l]
__device__ float g_cosT[HD_ * N_];

__device__ __forceinline__ float elu1(float x) {
    return x > 0.f ? x + 1.f : expf(x);
}

// ---------------- trig transpose: (N,32) -> (32,N) ----------------
__global__ void trig_transpose_kernel(const float* __restrict__ sinp,
                                      const float* __restrict__ cosp) {
    __shared__ float ts[32][33], tc[32][33];
    int l0 = blockIdx.x * 32;
    int t  = threadIdx.x;
    int c  = t & 31, r = t >> 5;   // r in 0..7
#pragma unroll
    for (int rr = 0; rr < 4; rr++) {
        int l = r + rr * 8;
        ts[l][c] = sinp[(size_t)(l0 + l) * HD_ + c];
        tc[l][c] = cosp[(size_t)(l0 + l) * HD_ + c];
    }
    __syncthreads();
#pragma unroll
    for (int rr = 0; rr < 4; rr++) {
        int d = r + rr * 8;
        g_sinT[(size_t)d * N_ + l0 + c] = ts[c][d];
        g_cosT[(size_t)d * N_ + l0 + c] = tc[c][d];
    }
}

// ---------------- GEMM core: C[M,Nn] = A[M,K] @ B[K,Nn] + bias[M] ----------------
// 128x128 tile, BK=16, 256 threads, 8x8 per thread in 2x2 groups of 4 (conflict-free).
__device__ __forceinline__ void gemm_core(
    const float* __restrict__ A, const float* __restrict__ Bb,
    const float* __restrict__ bias, float* __restrict__ Cb,
    int M, int K, int Nn)
{
    __shared__ float As[16][129];   // [k][m], scalar access
    __shared__ float Bs[16][132];   // [k][n], float4 access (528B rows, 16B aligned)

    int t  = threadIdx.x;
    int m0 = blockIdx.y * 128;
    int n0 = blockIdx.x * 128;
    int tx = t & 15;      // n group
    int ty = t >> 4;      // m group

    float acc[8][8];
#pragma unroll
    for (int i = 0; i < 8; i++)
#pragma unroll
        for (int j = 0; j < 8; j++) acc[i][j] = 0.f;

    int ar  = t >> 2;          // 0..63
    int ac4 = (t & 3) * 4;     // 0,4,8,12
    int br  = t >> 5;          // 0..7
    int bc4 = (t & 31) * 4;    // 0..124

    for (int k0 = 0; k0 < K; k0 += 16) {
        float4 a0 = *(const float4*)&A[(size_t)(m0 + ar) * K + k0 + ac4];
        float4 a1 = *(const float4*)&A[(size_t)(m0 + ar + 64) * K + k0 + ac4];
        float4 b0 = *(const float4*)&Bb[(size_t)(k0 + br) * Nn + n0 + bc4];
        float4 b1 = *(const float4*)&Bb[(size_t)(k0 + br + 8) * Nn + n0 + bc4];

        As[ac4 + 0][ar] = a0.x; As[ac4 + 1][ar] = a0.y;
        As[ac4 + 2][ar] = a0.z; As[ac4 + 3][ar] = a0.w;
        As[ac4 + 0][ar + 64] = a1.x; As[ac4 + 1][ar + 64] = a1.y;
        As[ac4 + 2][ar + 64] = a1.z; As[ac4 + 3][ar + 64] = a1.w;
        *(float4*)&Bs[br][bc4]     = b0;
        *(float4*)&Bs[br + 8][bc4] = b1;
        __syncthreads();

#pragma unroll
        for (int kk = 0; kk < 16; kk++) {
            float av[8], bv[8];
#pragma unroll
            for (int i = 0; i < 4; i++) {
                av[i]     = As[kk][ty * 4 + i];
                av[i + 4] = As[kk][64 + ty * 4 + i];
            }
            float4 bq0 = *(const float4*)&Bs[kk][tx * 4];
            float4 bq1 = *(const float4*)&Bs[kk][64 + tx * 4];
            bv[0] = bq0.x; bv[1] = bq0.y; bv[2] = bq0.z; bv[3] = bq0.w;
            bv[4] = bq1.x; bv[5] = bq1.y; bv[6] = bq1.z; bv[7] = bq1.w;
#pragma unroll
            for (int i = 0; i < 8; i++)
#pragma unroll
                for (int j = 0; j < 8; j++)
                    acc[i][j] = fmaf(av[i], bv[j], acc[i][j]);
        }
        __syncthreads();
    }

#pragma unroll
    for (int ih = 0; ih < 2; ih++)
#pragma unroll
        for (int ii = 0; ii < 4; ii++) {
            int m = m0 + ih * 64 + ty * 4 + ii;
            float bs = bias[m];
            int i = ih * 4 + ii;
#pragma unroll
            for (int jh = 0; jh < 2; jh++) {
                float4 v;
                v.x = acc[i][jh * 4 + 0] + bs;
                v.y = acc[i][jh * 4 + 1] + bs;
                v.z = acc[i][jh * 4 + 2] + bs;
                v.w = acc[i][jh * 4 + 3] + bs;
                *(float4*)&Cb[(size_t)m * Nn + n0 + jh * 64 + tx * 4] = v;
            }
        }
}

__global__ void gemm1_kernel(const float* __restrict__ x,
                             const float* __restrict__ w,
                             const float* __restrict__ bias) {
    int b = blockIdx.z;
    gemm_core(w, x + (size_t)b * C_ * N_, bias,
              g_qkvo + (size_t)b * 4 * C_ * N_, 4 * C_, C_, N_);
}

__global__ void gemm2_kernel(float* __restrict__ out,
                             const float* __restrict__ w,
                             const float* __restrict__ bias) {
    int b = blockIdx.z;
    gemm_core(w, g_res + (size_t)b * C_ * N_, bias,
              out + (size_t)b * C_ * N_, C_, C_, N_);
}

// ---------------- kmean (elu+1 of k) and vmean, per channel ----------------
__global__ void means_kernel() {
    int idx = blockIdx.x;
    int b = idx >> 8, ch = idx & 255;
    const float* kp = g_qkvo + (size_t)(b * 1024 + 256 + ch) * N_;
    const float* vp = g_qkvo + (size_t)(b * 1024 + 512 + ch) * N_;
    float ks = 0.f, vs = 0.f;
    for (int n = threadIdx.x; n < N_; n += 256) {
        ks += elu1(kp[n]);
        vs += vp[n];
    }
    __shared__ float sk[256], sv[256];
    sk[threadIdx.x] = ks; sv[threadIdx.x] = vs;
    __syncthreads();
    for (int s = 128; s > 0; s >>= 1) {
        if (threadIdx.x < s) {
            sk[threadIdx.x] += sk[threadIdx.x + s];
            sv[threadIdx.x] += sv[threadIdx.x + s];
        }
        __syncthreads();
    }
    if (threadIdx.x == 0) {
        g_kmean[b * 256 + ch] = sk[0] * (1.f / N_);
        g_vmean[b * 256 + ch] = sv[0] * (1.f / N_);
    }
}

// ---------------- kv[d][e] = s^2 * sum_l ks[d][l] * v[e][l] ----------------
// ks = theta_shift(elu(k)+1).  One block per (b,h).
__global__ void kv_kernel() {
    int bh = blockIdx.x;               // b*8 + h
    int b = bh >> 3, h = bh & 7;
    const float* kbase = g_qkvo + (size_t)(b * 1024 + 256 + h * 32) * N_;
    const float* vbase = g_qkvo + (size_t)(b * 1024 + 512 + h * 32) * N_;
    __shared__ float ks[32][129];
    __shared__ float vs[32][129];
    int t = threadIdx.x;
    int d  = t >> 3;            // 0..31
    int e0 = (t & 7) * 4;       // 0,4,...,28
    float acc0 = 0.f, acc1 = 0.f, acc2 = 0.f, acc3 = 0.f;

    for (int l0 = 0; l0 < N_; l0 += 128) {
        // load + elu(k)+1, raw v
#pragma unroll
        for (int it = 0; it < 4; it++) {
            int lin = t + it * 256;
            int r  = lin >> 5;
            int c4 = (lin & 31) * 4;
            float4 kq = *(const float4*)&kbase[(size_t)r * N_ + l0 + c4];
            ks[r][c4 + 0] = elu1(kq.x); ks[r][c4 + 1] = elu1(kq.y);
            ks[r][c4 + 2] = elu1(kq.z); ks[r][c4 + 3] = elu1(kq.w);
            float4 vq = *(const float4*)&vbase[(size_t)r * N_ + l0 + c4];
            vs[r][c4 + 0] = vq.x; vs[r][c4 + 1] = vq.y;
            vs[r][c4 + 2] = vq.z; vs[r][c4 + 3] = vq.w;
        }
        __syncthreads();
        // theta shift in place: (pair, l) per thread
#pragma unroll
        for (int it = 0; it < 8; it++) {
            int lin = t + it * 256;
            int pr = lin >> 7;          // 0..15 over the 8 its? (2048 items)
            int l  = lin & 127;
            int lg = l0 + l;
            float x0 = ks[2 * pr][l], x1 = ks[2 * pr + 1][l];
            float s0 = g_sinT[(size_t)(2 * pr) * N_ + lg];
            float c0 = g_cosT[(size_t)(2 * pr) * N_ + lg];
            float s1 = g_sinT[(size_t)(2 * pr + 1) * N_ + lg];
            float c1 = g_cosT[(size_t)(2 * pr + 1) * N_ + lg];
            ks[2 * pr][l]     = fmaf(x0, c0, -x1 * s0);
            ks[2 * pr + 1][l] = fmaf(x1, c1,  x0 * s1);
        }
        __syncthreads();
#pragma unroll 4
        for (int l = 0; l < 128; l++) {
            float kd = ks[d][l];
            acc0 = fmaf(kd, vs[e0 + 0][l], acc0);
            acc1 = fmaf(kd, vs[e0 + 1][l], acc1);
            acc2 = fmaf(kd, vs[e0 + 2][l], acc2);
            acc3 = fmaf(kd, vs[e0 + 3][l], acc3);
        }
        __syncthreads();
    }
    const float S2 = SCALE_ / (float)N_;
    float* kvp = g_kv + ((size_t)bh * 32 + d) * 32 + e0;
    kvp[0] = acc0 * S2; kvp[1] = acc1 * S2;
    kvp[2] = acc2 * S2; kvp[3] = acc3 * S2;
}

// ---------------- res[e][l] = (qs @ kv)[l][e]*(1+1/(z+1e-6)) - z*vmean[e] ----------------
// block: (l-tile of 128) x (b*8+h)
__global__ void res_kernel() {
    int l0 = blockIdx.x * 128;
    int bh = blockIdx.y;
    int b = bh >> 3, h = bh & 7;
    const float* qbase = g_qkvo + (size_t)(b * 1024 + h * 32) * N_;
    float* rbase = g_res + (size_t)(b * 256 + h * 32) * N_;

    __shared__ float qs[32][129];
    __shared__ float kvS[32][32];   // [d][e]
    __shared__ float zS[128];
    __shared__ float kmS[32], vmS[32];
    int t = threadIdx.x;

    if (t < 32) {
        kmS[t] = g_kmean[b * 256 + h * 32 + t];
        vmS[t] = g_vmean[b * 256 + h * 32 + t];
    }
#pragma unroll
    for (int it = 0; it < 4; it++) {
        int lin = t + it * 256;     // 0..1023
        kvS[lin >> 5][lin & 31] = g_kv[(size_t)bh * 1024 + lin];
    }
    // load q + elu
#pragma unroll
    for (int it = 0; it < 4; it++) {
        int lin = t + it * 256;
        int r  = lin >> 5;
        int c4 = (lin & 31) * 4;
        float4 q = *(const float4*)&qbase[(size_t)r * N_ + l0 + c4];
        qs[r][c4 + 0] = elu1(q.x); qs[r][c4 + 1] = elu1(q.y);
        qs[r][c4 + 2] = elu1(q.z); qs[r][c4 + 3] = elu1(q.w);
    }
    __syncthreads();
    // z from pre-RoPE q
    if (t < 128) {
        float a = 0.f;
#pragma unroll
        for (int d = 0; d < 32; d++) a = fmaf(qs[d][t], kmS[d], a);
        zS[t] = a * SCALE_;
    }
    __syncthreads();
    // theta shift in place
#pragma unroll
    for (int it = 0; it < 8; it++) {
        int lin = t + it * 256;
        int pr = lin >> 7;
        int l  = lin & 127;
        int lg = l0 + l;
        float x0 = qs[2 * pr][l], x1 = qs[2 * pr + 1][l];
        float s0 = g_sinT[(size_t)(2 * pr) * N_ + lg];
        float c0 = g_cosT[(size_t)(2 * pr) * N_ + lg];
        float s1 = g_sinT[(size_t)(2 * pr + 1) * N_ + lg];
        float c1 = g_cosT[(size_t)(2 * pr + 1) * N_ + lg];
        qs[2 * pr][l]     = fmaf(x0, c0, -x1 * s0);
        qs[2 * pr + 1][l] = fmaf(x1, c1,  x0 * s1);
    }
    __syncthreads();
    // matmul + pointwise: e = t&31, lc = t>>5 owns 16 l's
    int e  = t & 31;
    int lb = (t >> 5) * 16;
    float acc[16];
#pragma unroll
    for (int j = 0; j < 16; j++) acc[j] = 0.f;
#pragma unroll
    for (int d = 0; d < 32; d++) {
        float kd = kvS[d][e];
#pragma unroll
        for (int j = 0; j < 16; j++)
            acc[j] = fmaf(kd, qs[d][lb + j], acc[j]);
    }
    float vm = vmS[e];
    float outv[16];
#pragma unroll
    for (int j = 0; j < 16; j++) {
        float z = zS[lb + j];
        float fac = 1.f + 1.f / (z + 1e-6f);
        outv[j] = acc[j] * fac - z * vm;
    }
    float* wp = rbase + (size_t)e * N_ + l0 + lb;
#pragma unroll
    for (int j4 = 0; j4 < 4; j4++) {
        float4 v;
        v.x = outv[j4 * 4 + 0]; v.y = outv[j4 * 4 + 1];
        v.z = outv[j4 * 4 + 2]; v.w = outv[j4 * 4 + 3];
        *(float4*)&wp[j4 * 4] = v;
    }
}

// ---------------- lepe (5x5 depthwise, pad 2) + gate: res = (res + lepe) * o ----------------
__global__ void lepe_gate_kernel(const float* __restrict__ w_lepe,
                                 const float* __restrict__ b_lepe) {
    int tile = blockIdx.x;          // 4 tiles of 16 rows
    int c = blockIdx.y;
    int b = blockIdx.z;
    const float* vch = g_qkvo + (size_t)(b * 1024 + 512 + c) * N_;
    const float* och = g_qkvo + (size_t)(b * 1024 + 768 + c) * N_;
    float* rch = g_res + (size_t)(b * 256 + c) * N_;

    __shared__ float sv[20][68];
    __shared__ float wS[25];
    int t = threadIdx.x;
    if (t < 25) wS[t] = w_lepe[c * 25 + t];
    int y0 = tile * 16;
    for (int lin = t; lin < 20 * 68; lin += 256) {
        int ry = lin / 68, rx = lin - ry * 68;
        int gy = y0 + ry - 2, gx = rx - 2;
        float v = 0.f;
        if (gy >= 0 && gy < 64 && gx >= 0 && gx < 64) v = vch[gy * 64 + gx];
        sv[ry][rx] = v;
    }
    __syncthreads();
    float bl = b_lepe[c];
#pragma unroll
    for (int it = 0; it < 4; it++) {
        int lin = t + it * 256;
        int py = lin >> 6, px = lin & 63;
        float a = bl;
#pragma unroll
        for (int ky = 0; ky < 5; ky++)
#pragma unroll
            for (int kx = 0; kx < 5; kx++)
                a = fmaf(sv[py + ky][px + kx], wS[ky * 5 + kx], a);
        int gi = (y0 + py) * 64 + px;
        rch[gi] = (rch[gi] + a) * och[gi];
    }
}

// ---------------- launch ----------------
extern "C" void kernel_launch(void* const* d_in, const int* in_sizes, int n_in,
                              void* d_out, int out_size) {
    (void)in_sizes; (void)n_in; (void)out_size;
    const float* x      = (const float*)d_in[0];
    const float* sinp   = (const float*)d_in[1];
    const float* cosp   = (const float*)d_in[2];
    const float* w_qkvo = (const float*)d_in[3];
    const float* b_qkvo = (const float*)d_in[4];
    const float* w_lepe = (const float*)d_in[5];
    const float* b_lepe = (const float*)d_in[6];
    const float* w_proj = (const float*)d_in[7];
    const float* b_proj = (const float*)d_in[8];
    float* out = (float*)d_out;

    trig_transpose_kernel<<<N_ / 32, 256>>>(sinp, cosp);
    gemm1_kernel<<<dim3(N_ / 128, 8, B_), 256>>>(x, w_qkvo, b_qkvo);
    means_kernel<<<B_ * C_, 256>>>();
    kv_kernel<<<B_ * HEADS_, 256>>>();
    res_kernel<<<dim3(N_ / 128, B_ * HEADS_), 256>>>();
    lepe_gate_kernel<<<dim3(4, C_, B_), 256>>>(w_lepe, b_lepe);
    gemm2_kernel<<<dim3(N_ / 128, 2, B_), 256>>>(out, w_proj, b_proj);
}

// round 3
// speedup vs baseline: 1.2864x; 1.2864x over previous
#include <cuda_runtime.h>
#include <math.h>

#define B_ 8
#define C_ 256
#define H_IMG 64
#define W_IMG 64
#define N_ 4096
#define HEADS_ 8
#define HD_ 32
#define SCALE_ 0.17677669529663687f   /* 32^-0.5 */
#define KV_SPLIT 32                    /* l-tiles of 128 */

// ---------------- scratch (device globals: no allocation allowed) ----------------
__device__ float g_qkvo[(size_t)B_ * 4 * C_ * N_];   // 134 MB: [b][o(1024)][n]
__device__ float g_res [(size_t)B_ * C_ * N_];       // 33.5 MB: [b][c][n]
__device__ float g_kv  [B_ * HEADS_ * HD_ * HD_];    // [bh][d][e]
__device__ float g_kvp [B_ * HEADS_ * KV_SPLIT * HD_ * HD_];  // partials
__device__ float g_kmean[B_ * C_];
__device__ float g_vmean[B_ * C_];
__device__ float g_sinT[HD_ * N_];                   // transposed trig: [d][l]
__device__ float g_cosT[HD_ * N_];

__device__ __forceinline__ float elu1(float x) {
    return x > 0.f ? x + 1.f : expf(x);
}

// ---------------- trig transpose: (N,32) -> (32,N) ----------------
__global__ void trig_transpose_kernel(const float* __restrict__ sinp,
                                      const float* __restrict__ cosp) {
    __shared__ float ts[32][33], tc[32][33];
    int l0 = blockIdx.x * 32;
    int t  = threadIdx.x;
    int c  = t & 31, r = t >> 5;   // r in 0..7
#pragma unroll
    for (int rr = 0; rr < 4; rr++) {
        int l = r + rr * 8;
        ts[l][c] = sinp[(size_t)(l0 + l) * HD_ + c];
        tc[l][c] = cosp[(size_t)(l0 + l) * HD_ + c];
    }
    __syncthreads();
#pragma unroll
    for (int rr = 0; rr < 4; rr++) {
        int d = r + rr * 8;
        g_sinT[(size_t)d * N_ + l0 + c] = ts[c][d];
        g_cosT[(size_t)d * N_ + l0 + c] = tc[c][d];
    }
}

// ---------------- GEMM core: C[M,Nn] = A[M,K] @ B[K,Nn] + bias[M] ----------------
// 128x128 tile, BK=16, 256 threads, 8x8/thread, double-buffered smem pipeline.
__device__ __forceinline__ void gemm_core(
    const float* __restrict__ A, const float* __restrict__ Bb,
    const float* __restrict__ bias, float* __restrict__ Cb,
    int M, int K, int Nn)
{
    __shared__ float As[2][16][129];   // [buf][k][m]
    __shared__ float Bs[2][16][132];   // [buf][k][n]

    int t  = threadIdx.x;
    int m0 = blockIdx.y * 128;
    int n0 = blockIdx.x * 128;
    int tx = t & 15;      // n group
    int ty = t >> 4;      // m group

    float acc[8][8];
#pragma unroll
    for (int i = 0; i < 8; i++)
#pragma unroll
        for (int j = 0; j < 8; j++) acc[i][j] = 0.f;

    int ar  = t >> 2;          // 0..63
    int ac4 = (t & 3) * 4;     // 0,4,8,12
    int br  = t >> 5;          // 0..7
    int bc4 = (t & 31) * 4;    // 0..124

    const float* Apr  = &A[(size_t)(m0 + ar) * K + ac4];
    const float* Apr2 = &A[(size_t)(m0 + ar + 64) * K + ac4];
    const float* Bpr  = &Bb[(size_t)br * Nn + n0 + bc4];
    const float* Bpr2 = &Bb[(size_t)(br + 8) * Nn + n0 + bc4];

    // preload slab 0
    {
        float4 a0 = *(const float4*)Apr;
        float4 a1 = *(const float4*)Apr2;
        float4 b0 = *(const float4*)Bpr;
        float4 b1 = *(const float4*)Bpr2;
        As[0][ac4 + 0][ar] = a0.x; As[0][ac4 + 1][ar] = a0.y;
        As[0][ac4 + 2][ar] = a0.z; As[0][ac4 + 3][ar] = a0.w;
        As[0][ac4 + 0][ar + 64] = a1.x; As[0][ac4 + 1][ar + 64] = a1.y;
        As[0][ac4 + 2][ar + 64] = a1.z; As[0][ac4 + 3][ar + 64] = a1.w;
        *(float4*)&Bs[0][br][bc4]     = b0;
        *(float4*)&Bs[0][br + 8][bc4] = b1;
    }
    __syncthreads();

    int buf = 0;
    for (int k0 = 0; k0 < K; k0 += 16) {
        float4 na0, na1, nb0, nb1;
        bool has_next = (k0 + 16 < K);
        if (has_next) {
            na0 = *(const float4*)&Apr [k0 + 16];
            na1 = *(const float4*)&Apr2[k0 + 16];
            nb0 = *(const float4*)&Bpr [(size_t)(k0 + 16) * Nn];
            nb1 = *(const float4*)&Bpr2[(size_t)(k0 + 16) * Nn];
        }

#pragma unroll
        for (int kk = 0; kk < 16; kk++) {
            float av[8], bv[8];
#pragma unroll
            for (int i = 0; i < 4; i++) {
                av[i]     = As[buf][kk][ty * 4 + i];
                av[i + 4] = As[buf][kk][64 + ty * 4 + i];
            }
            float4 bq0 = *(const float4*)&Bs[buf][kk][tx * 4];
            float4 bq1 = *(const float4*)&Bs[buf][kk][64 + tx * 4];
            bv[0] = bq0.x; bv[1] = bq0.y; bv[2] = bq0.z; bv[3] = bq0.w;
            bv[4] = bq1.x; bv[5] = bq1.y; bv[6] = bq1.z; bv[7] = bq1.w;
#pragma unroll
            for (int i = 0; i < 8; i++)
#pragma unroll
                for (int j = 0; j < 8; j++)
                    acc[i][j] = fmaf(av[i], bv[j], acc[i][j]);
        }

        if (has_next) {
            int nb = buf ^ 1;
            As[nb][ac4 + 0][ar] = na0.x; As[nb][ac4 + 1][ar] = na0.y;
            As[nb][ac4 + 2][ar] = na0.z; As[nb][ac4 + 3][ar] = na0.w;
            As[nb][ac4 + 0][ar + 64] = na1.x; As[nb][ac4 + 1][ar + 64] = na1.y;
            As[nb][ac4 + 2][ar + 64] = na1.z; As[nb][ac4 + 3][ar + 64] = na1.w;
            *(float4*)&Bs[nb][br][bc4]     = nb0;
            *(float4*)&Bs[nb][br + 8][bc4] = nb1;
            __syncthreads();
            buf = nb;
        }
    }

#pragma unroll
    for (int ih = 0; ih < 2; ih++)
#pragma unroll
        for (int ii = 0; ii < 4; ii++) {
            int m = m0 + ih * 64 + ty * 4 + ii;
            float bs = bias[m];
            int i = ih * 4 + ii;
#pragma unroll
            for (int jh = 0; jh < 2; jh++) {
                float4 v;
                v.x = acc[i][jh * 4 + 0] + bs;
                v.y = acc[i][jh * 4 + 1] + bs;
                v.z = acc[i][jh * 4 + 2] + bs;
                v.w = acc[i][jh * 4 + 3] + bs;
                *(float4*)&Cb[(size_t)m * Nn + n0 + jh * 64 + tx * 4] = v;
            }
        }
}

__global__ void gemm1_kernel(const float* __restrict__ x,
                             const float* __restrict__ w,
                             const float* __restrict__ bias) {
    int b = blockIdx.z;
    gemm_core(w, x + (size_t)b * C_ * N_, bias,
              g_qkvo + (size_t)b * 4 * C_ * N_, 4 * C_, C_, N_);
}

__global__ void gemm2_kernel(float* __restrict__ out,
                             const float* __restrict__ w,
                             const float* __restrict__ bias) {
    int b = blockIdx.z;
    gemm_core(w, g_res + (size_t)b * C_ * N_, bias,
              out + (size_t)b * C_ * N_, C_, C_, N_);
}

// ---------------- kmean (elu+1 of k) and vmean, per channel ----------------
__global__ void means_kernel() {
    int idx = blockIdx.x;
    int b = idx >> 8, ch = idx & 255;
    const float* kp = g_qkvo + (size_t)(b * 1024 + 256 + ch) * N_;
    const float* vp = g_qkvo + (size_t)(b * 1024 + 512 + ch) * N_;
    float ks = 0.f, vs = 0.f;
    for (int n = threadIdx.x; n < N_; n += 256) {
        ks += elu1(kp[n]);
        vs += vp[n];
    }
    __shared__ float sk[256], sv[256];
    sk[threadIdx.x] = ks; sv[threadIdx.x] = vs;
    __syncthreads();
    for (int s = 128; s > 0; s >>= 1) {
        if (threadIdx.x < s) {
            sk[threadIdx.x] += sk[threadIdx.x + s];
            sv[threadIdx.x] += sv[threadIdx.x + s];
        }
        __syncthreads();
    }
    if (threadIdx.x == 0) {
        g_kmean[b * 256 + ch] = sk[0] * (1.f / N_);
        g_vmean[b * 256 + ch] = sv[0] * (1.f / N_);
    }
}

// ---------------- kv partials: one block per (split, b*h) ----------------
__global__ void kv_split_kernel() {
    int split = blockIdx.x;            // 0..31
    int bh = blockIdx.y;               // b*8 + h
    int b = bh >> 3, h = bh & 7;
    int l0 = split * 128;
    const float* kbase = g_qkvo + (size_t)(b * 1024 + 256 + h * 32) * N_;
    const float* vbase = g_qkvo + (size_t)(b * 1024 + 512 + h * 32) * N_;
    __shared__ float ks[32][129];
    __shared__ float vs[32][129];
    int t = threadIdx.x;
    int d  = t >> 3;            // 0..31
    int e0 = (t & 7) * 4;       // 0,4,...,28

#pragma unroll
    for (int it = 0; it < 4; it++) {
        int lin = t + it * 256;
        int r  = lin >> 5;
        int c4 = (lin & 31) * 4;
        float4 kq = *(const float4*)&kbase[(size_t)r * N_ + l0 + c4];
        ks[r][c4 + 0] = elu1(kq.x); ks[r][c4 + 1] = elu1(kq.y);
        ks[r][c4 + 2] = elu1(kq.z); ks[r][c4 + 3] = elu1(kq.w);
        float4 vq = *(const float4*)&vbase[(size_t)r * N_ + l0 + c4];
        vs[r][c4 + 0] = vq.x; vs[r][c4 + 1] = vq.y;
        vs[r][c4 + 2] = vq.z; vs[r][c4 + 3] = vq.w;
    }
    __syncthreads();
#pragma unroll
    for (int it = 0; it < 8; it++) {
        int lin = t + it * 256;
        int pr = lin >> 7;
        int l  = lin & 127;
        int lg = l0 + l;
        float x0 = ks[2 * pr][l], x1 = ks[2 * pr + 1][l];
        float s0 = g_sinT[(size_t)(2 * pr) * N_ + lg];
        float c0 = g_cosT[(size_t)(2 * pr) * N_ + lg];
        float s1 = g_sinT[(size_t)(2 * pr + 1) * N_ + lg];
        float c1 = g_cosT[(size_t)(2 * pr + 1) * N_ + lg];
        ks[2 * pr][l]     = fmaf(x0, c0, -x1 * s0);
        ks[2 * pr + 1][l] = fmaf(x1, c1,  x0 * s1);
    }
    __syncthreads();
    float acc0 = 0.f, acc1 = 0.f, acc2 = 0.f, acc3 = 0.f;
#pragma unroll 4
    for (int l = 0; l < 128; l++) {
        float kd = ks[d][l];
        acc0 = fmaf(kd, vs[e0 + 0][l], acc0);
        acc1 = fmaf(kd, vs[e0 + 1][l], acc1);
        acc2 = fmaf(kd, vs[e0 + 2][l], acc2);
        acc3 = fmaf(kd, vs[e0 + 3][l], acc3);
    }
    float* pp = g_kvp + ((size_t)bh * KV_SPLIT + split) * 1024 + d * 32 + e0;
    pp[0] = acc0; pp[1] = acc1; pp[2] = acc2; pp[3] = acc3;
}

// ---------------- kv reduce: fixed-order sum over the 32 split partials ----------------
__global__ void kv_reduce_kernel() {
    int bh = blockIdx.x;
    int i = threadIdx.x;    // 0..1023
    const float* pp = g_kvp + (size_t)bh * KV_SPLIT * 1024 + i;
    float a = 0.f;
#pragma unroll
    for (int s = 0; s < KV_SPLIT; s++) a += pp[(size_t)s * 1024];
    const float S2 = SCALE_ / (float)N_;
    g_kv[(size_t)bh * 1024 + i] = a * S2;
}

// ---------------- res[e][l] = (qs @ kv)[l][e]*(1+1/(z+1e-6)) - z*vmean[e] ----------------
__global__ void res_kernel() {
    int l0 = blockIdx.x * 128;
    int bh = blockIdx.y;
    int b = bh >> 3, h = bh & 7;
    const float* qbase = g_qkvo + (size_t)(b * 1024 + h * 32) * N_;
    float* rbase = g_res + (size_t)(b * 256 + h * 32) * N_;

    __shared__ float qs[32][129];
    __shared__ float kvS[32][32];   // [d][e]
    __shared__ float zS[128];
    __shared__ float kmS[32], vmS[32];
    int t = threadIdx.x;

    if (t < 32) {
        kmS[t] = g_kmean[b * 256 + h * 32 + t];
        vmS[t] = g_vmean[b * 256 + h * 32 + t];
    }
#pragma unroll
    for (int it = 0; it < 4; it++) {
        int lin = t + it * 256;     // 0..1023
        kvS[lin >> 5][lin & 31] = g_kv[(size_t)bh * 1024 + lin];
    }
#pragma unroll
    for (int it = 0; it < 4; it++) {
        int lin = t + it * 256;
        int r  = lin >> 5;
        int c4 = (lin & 31) * 4;
        float4 q = *(const float4*)&qbase[(size_t)r * N_ + l0 + c4];
        qs[r][c4 + 0] = elu1(q.x); qs[r][c4 + 1] = elu1(q.y);
        qs[r][c4 + 2] = elu1(q.z); qs[r][c4 + 3] = elu1(q.w);
    }
    __syncthreads();
    if (t < 128) {
        float a = 0.f;
#pragma unroll
        for (int d = 0; d < 32; d++) a = fmaf(qs[d][t], kmS[d], a);
        zS[t] = a * SCALE_;
    }
    __syncthreads();
#pragma unroll
    for (int it = 0; it < 8; it++) {
        int lin = t + it * 256;
        int pr = lin >> 7;
        int l  = lin & 127;
        int lg = l0 + l;
        float x0 = qs[2 * pr][l], x1 = qs[2 * pr + 1][l];
        float s0 = g_sinT[(size_t)(2 * pr) * N_ + lg];
        float c0 = g_cosT[(size_t)(2 * pr) * N_ + lg];
        float s1 = g_sinT[(size_t)(2 * pr + 1) * N_ + lg];
        float c1 = g_cosT[(size_t)(2 * pr + 1) * N_ + lg];
        qs[2 * pr][l]     = fmaf(x0, c0, -x1 * s0);
        qs[2 * pr + 1][l] = fmaf(x1, c1,  x0 * s1);
    }
    __syncthreads();
    int e  = t & 31;
    int lb = (t >> 5) * 16;
    float acc[16];
#pragma unroll
    for (int j = 0; j < 16; j++) acc[j] = 0.f;
#pragma unroll
    for (int d = 0; d < 32; d++) {
        float kd = kvS[d][e];
#pragma unroll
        for (int j = 0; j < 16; j++)
            acc[j] = fmaf(kd, qs[d][lb + j], acc[j]);
    }
    float vm = vmS[e];
    float outv[16];
#pragma unroll
    for (int j = 0; j < 16; j++) {
        float z = zS[lb + j];
        float fac = 1.f + 1.f / (z + 1e-6f);
        outv[j] = acc[j] * fac - z * vm;
    }
    float* wp = rbase + (size_t)e * N_ + l0 + lb;
#pragma unroll
    for (int j4 = 0; j4 < 4; j4++) {
        float4 v;
        v.x = outv[j4 * 4 + 0]; v.y = outv[j4 * 4 + 1];
        v.z = outv[j4 * 4 + 2]; v.w = outv[j4 * 4 + 3];
        *(float4*)&wp[j4 * 4] = v;
    }
}

// ---------------- lepe (5x5 depthwise, pad 2) + gate: res = (res + lepe) * o ----------------
__global__ void lepe_gate_kernel(const float* __restrict__ w_lepe,
                                 const float* __restrict__ b_lepe) {
    int tile = blockIdx.x;          // 4 tiles of 16 rows
    int c = blockIdx.y;
    int b = blockIdx.z;
    const float* vch = g_qkvo + (size_t)(b * 1024 + 512 + c) * N_;
    const float* och = g_qkvo + (size_t)(b * 1024 + 768 + c) * N_;
    float* rch = g_res + (size_t)(b * 256 + c) * N_;

    __shared__ float sv[20][68];
    __shared__ float wS[25];
    int t = threadIdx.x;
    if (t < 25) wS[t] = w_lepe[c * 25 + t];
    int y0 = tile * 16;
    for (int lin = t; lin < 20 * 68; lin += 256) {
        int ry = lin / 68, rx = lin - ry * 68;
        int gy = y0 + ry - 2, gx = rx - 2;
        float v = 0.f;
        if (gy >= 0 && gy < 64 && gx >= 0 && gx < 64) v = vch[gy * 64 + gx];
        sv[ry][rx] = v;
    }
    __syncthreads();
    float bl = b_lepe[c];
#pragma unroll
    for (int it = 0; it < 4; it++) {
        int lin = t + it * 256;
        int py = lin >> 6, px = lin & 63;
        float a = bl;
#pragma unroll
        for (int ky = 0; ky < 5; ky++)
#pragma unroll
            for (int kx = 0; kx < 5; kx++)
                a = fmaf(sv[py + ky][px + kx], wS[ky * 5 + kx], a);
        int gi = (y0 + py) * 64 + px;
        rch[gi] = (rch[gi] + a) * och[gi];
    }
}

// ---------------- launch ----------------
extern "C" void kernel_launch(void* const* d_in, const int* in_sizes, int n_in,
                              void* d_out, int out_size) {
    (void)in_sizes; (void)n_in; (void)out_size;
    const float* x      = (const float*)d_in[0];
    const float* sinp   = (const float*)d_in[1];
    const float* cosp   = (const float*)d_in[2];
    const float* w_qkvo = (const float*)d_in[3];
    const float* b_qkvo = (const float*)d_in[4];
    const float* w_lepe = (const float*)d_in[5];
    const float* b_lepe = (const float*)d_in[6];
    const float* w_proj = (const float*)d_in[7];
    const float* b_proj = (const float*)d_in[8];
    float* out = (float*)d_out;

    trig_transpose_kernel<<<N_ / 32, 256>>>(sinp, cosp);
    gemm1_kernel<<<dim3(N_ / 128, 8, B_), 256>>>(x, w_qkvo, b_qkvo);
    means_kernel<<<B_ * C_, 256>>>();
    kv_split_kernel<<<dim3(KV_SPLIT, B_ * HEADS_), 256>>>();
    kv_reduce_kernel<<<B_ * HEADS_, 1024>>>();
    res_kernel<<<dim3(N_ / 128, B_ * HEADS_), 256>>>();
    lepe_gate_kernel<<<dim3(4, C_, B_), 256>>>(w_lepe, b_lepe);
    gemm2_kernel<<<dim3(N_ / 128, 2, B_), 256>>>(out, w_proj, b_proj);
}